// round 1
// baseline (speedup 1.0000x reference)
#include <cuda_runtime.h>
#include <cstdint>
#include <cstddef>

// ---------------------------------------------------------------------------
// HeteroSAGEAttention on GB300 — round 1 (fp32 SIMT GEMM + vector-atomic scatter)
//
// Pipeline per edge-conv (x_src, x_tgt, edge_index, Ws, Wt, a):
//   psrc = x_src @ Ws            [N,128]   (tiled SGEMM)
//   ptgt = x_tgt @ Wt            [N,128]
//   s_src[n] = psrc[n] . a[0:128]          (warp-per-row dot)
//   s_tgt[n] = ptgt[n] . a[128:256]
//   per edge e: s2 = si[si[e]]; t = ti[e]
//     att = exp(leaky_relu(s_src[s2] + s_tgt[t], 0.2))
//     num[t] += att * psrc[s2]   (red.global.add.v4.f32, warp-per-edge)
//     den[t] += att
//   out[n] = relu(ptgt[n] + num[n]/(den[n]+1e-6))
// ---------------------------------------------------------------------------

#define NN 100000
#define HH 128
#define EE 500000
#define NH (NN * HH)          // 12,800,000 floats per node-feature buffer

// scratch: 8 node-feature buffers + 6 scalar-per-node buffers  (~412 MB)
__device__ float g_scratch[8ull * NH + 6ull * NN];

// ---------------------------------------------------------------------------
// SGEMM: C[M x BN] = A[M x K] @ W[K x BN] (+ bias).  BM=128, BK=16,
// 256 threads, TM=8 x TN=BN/16 register tile.  K must be a multiple of 16.
// ---------------------------------------------------------------------------
template <int BN>
__global__ __launch_bounds__(256) void sgemm_kernel(
    const float* __restrict__ A, const float* __restrict__ W,
    const float* __restrict__ bias, float* __restrict__ C, int M, int K)
{
    constexpr int BM = 128, BK = 16, TM = 8;
    constexpr int TN = BN / 16;

    __shared__ float As[BK][132];   // transposed A tile, padded (16B-aligned rows)
    __shared__ float Bs[BK][BN];

    const int tid = threadIdx.x;
    const int tx  = tid & 15;       // 0..15 column group
    const int ty  = tid >> 4;       // 0..15 row group
    const int m0  = blockIdx.x * BM;

    float acc[TM][TN];
#pragma unroll
    for (int i = 0; i < TM; i++)
#pragma unroll
        for (int j = 0; j < TN; j++) acc[i][j] = 0.f;

    for (int k0 = 0; k0 < K; k0 += BK) {
        // --- load A tile (128x16), coalesced float4, store transposed ---
#pragma unroll
        for (int t = 0; t < 2; t++) {
            int l   = tid + t * 256;        // 0..511 float4 index
            int row = l >> 2;               // 0..127
            int c4  = (l & 3) << 2;         // 0,4,8,12
            int gr  = m0 + row;
            float4 v = make_float4(0.f, 0.f, 0.f, 0.f);
            if (gr < M)
                v = __ldg((const float4*)(A + (size_t)gr * K + k0 + c4));
            As[c4 + 0][row] = v.x;
            As[c4 + 1][row] = v.y;
            As[c4 + 2][row] = v.z;
            As[c4 + 3][row] = v.w;
        }
        // --- load B tile (16xBN), coalesced float4 ---
        constexpr int BV = BK * BN / 4;
#pragma unroll
        for (int t = 0; t < BV / 256; t++) {
            int l = tid + t * 256;
            int r = l / (BN / 4);
            int c = (l % (BN / 4)) << 2;
            *(float4*)&Bs[r][c] =
                __ldg((const float4*)(W + (size_t)(k0 + r) * BN + c));
        }
        __syncthreads();

#pragma unroll
        for (int kk = 0; kk < BK; kk++) {
            float a[TM], b[TN];
            *(float4*)&a[0] = *(const float4*)&As[kk][ty * TM];
            *(float4*)&a[4] = *(const float4*)&As[kk][ty * TM + 4];
#pragma unroll
            for (int j = 0; j < TN; j += 4)
                *(float4*)&b[j] = *(const float4*)&Bs[kk][tx * TN + j];
#pragma unroll
            for (int i = 0; i < TM; i++)
#pragma unroll
                for (int j = 0; j < TN; j++)
                    acc[i][j] = fmaf(a[i], b[j], acc[i][j]);
        }
        __syncthreads();
    }

    // --- epilogue ---
#pragma unroll
    for (int i = 0; i < TM; i++) {
        int gr = m0 + ty * TM + i;
        if (gr >= M) continue;
#pragma unroll
        for (int j = 0; j < TN; j += 4) {
            float4 r;
            r.x = acc[i][j + 0];
            r.y = acc[i][j + 1];
            r.z = acc[i][j + 2];
            r.w = acc[i][j + 3];
            if (bias) {
                r.x += __ldg(bias + tx * TN + j + 0);
                r.y += __ldg(bias + tx * TN + j + 1);
                r.z += __ldg(bias + tx * TN + j + 2);
                r.w += __ldg(bias + tx * TN + j + 3);
            }
            *(float4*)(C + (size_t)gr * BN + tx * TN + j) = r;
        }
    }
}

// ---------------------------------------------------------------------------
// score: s[n] = P[n, 0:128] . a[0:128]   (warp per row)
// ---------------------------------------------------------------------------
__global__ __launch_bounds__(256) void score_kernel(
    const float* __restrict__ P, const float* __restrict__ a,
    float* __restrict__ s)
{
    int idx  = blockIdx.x * blockDim.x + threadIdx.x;
    int row  = idx >> 5;
    if (row >= NN) return;
    int lane = idx & 31;
    float4 p  = __ldg((const float4*)(P + (size_t)row * HH) + lane);
    float4 av = __ldg((const float4*)a + lane);
    float d = p.x * av.x + p.y * av.y + p.z * av.z + p.w * av.w;
#pragma unroll
    for (int o = 16; o; o >>= 1) d += __shfl_xor_sync(0xffffffffu, d, o);
    if (lane == 0) s[row] = d;
}

// ---------------------------------------------------------------------------
// edge: warp per edge; gather psrc[si[si[e]]], vector-atomic into num[ti[e]]
// ---------------------------------------------------------------------------
__global__ __launch_bounds__(256) void edge_kernel(
    const int* __restrict__ si, const int* __restrict__ ti,
    const float* __restrict__ sp, const float* __restrict__ ssrc,
    const float* __restrict__ stgt, float* __restrict__ num,
    float* __restrict__ den)
{
    int w = (blockIdx.x * blockDim.x + threadIdx.x) >> 5;
    if (w >= EE) return;
    int lane = threadIdx.x & 31;

    int s1 = __ldg(si + w);
    int t  = __ldg(ti + w);
    int s2 = __ldg(si + s1);              // reference quirk: src[si][si]

    float lg  = __ldg(ssrc + s2) + __ldg(stgt + t);
    float lr  = lg > 0.f ? lg : 0.2f * lg;
    float att = __expf(lr);

    float4 v = __ldg((const float4*)(sp + (size_t)s2 * HH) + lane);
    float4 r = make_float4(v.x * att, v.y * att, v.z * att, v.w * att);

    float* np = num + (size_t)t * HH + lane * 4;
    asm volatile("red.global.add.v4.f32 [%0], {%1,%2,%3,%4};"
                 :: "l"(np), "f"(r.x), "f"(r.y), "f"(r.z), "f"(r.w)
                 : "memory");
    if (lane == 0) atomicAdd(den + t, att);
}

// ---------------------------------------------------------------------------
// combine: out = relu(ptgt + num / (den + eps))
// ---------------------------------------------------------------------------
__global__ __launch_bounds__(256) void combine_kernel(
    const float* __restrict__ tp, const float* __restrict__ num,
    const float* __restrict__ den, float* __restrict__ of)
{
    int i = blockIdx.x * blockDim.x + threadIdx.x;   // float4 index
    if (i >= NN * (HH / 4)) return;
    int row = i / (HH / 4);
    float invd = 1.f / (den[row] + 1e-6f);
    float4 t = __ldg((const float4*)tp + i);
    float4 n = ((const float4*)num)[i];
    float4 r;
    r.x = fmaxf(fmaf(n.x, invd, t.x), 0.f);
    r.y = fmaxf(fmaf(n.y, invd, t.y), 0.f);
    r.z = fmaxf(fmaf(n.z, invd, t.z), 0.f);
    r.w = fmaxf(fmaf(n.w, invd, t.w), 0.f);
    ((float4*)of)[i] = r;
}

// ---------------------------------------------------------------------------
extern "C" void kernel_launch(void* const* d_in, const int* in_sizes, int n_in,
                              void* d_out, int out_size)
{
    const float* x_user     = (const float*)d_in[0];
    const float* x_spot     = (const float*)d_in[1];
    const int*   e_us       = (const int*)d_in[2];   // [2, E]
    const int*   e_su       = (const int*)d_in[3];
    const float* Ws_us0     = (const float*)d_in[4];
    const float* Wt_us0     = (const float*)d_in[5];
    const float* a_us0      = (const float*)d_in[6];
    const float* Ws_su0     = (const float*)d_in[7];
    const float* Wt_su0     = (const float*)d_in[8];
    const float* a_su0      = (const float*)d_in[9];
    const float* Ws_us1     = (const float*)d_in[10];
    const float* Wt_us1     = (const float*)d_in[11];
    const float* a_us1      = (const float*)d_in[12];
    const float* Ws_su1     = (const float*)d_in[13];
    const float* Wt_su1     = (const float*)d_in[14];
    const float* a_su1      = (const float*)d_in[15];
    const float* W_out_user = (const float*)d_in[16];
    const float* b_out_user = (const float*)d_in[17];
    const float* W_out_spot = (const float*)d_in[18];
    const float* b_out_spot = (const float*)d_in[19];

    float* base = nullptr;
    cudaGetSymbolAddress((void**)&base, g_scratch);

    float* pu    = base + 0ull * NH;   // src-proj for 'us' conv
    float* pts   = base + 1ull * NH;   // tgt-proj (spot) for 'us' conv
    float* ps    = base + 2ull * NH;   // src-proj for 'su' conv
    float* ptu   = base + 3ull * NH;   // tgt-proj (user) for 'su' conv
    float* num_s = base + 4ull * NH;
    float* num_u = base + 5ull * NH;
    float* h_u   = base + 6ull * NH;   // layer-0 relu'd user features
    float* h_s   = base + 7ull * NH;
    float* den_s = base + 8ull * NH;
    float* den_u = den_s + NN;
    float* s_src = den_u + NN;
    float* s_tgt = s_src + NN;

    float* out  = (float*)d_out;
    float* o_xu = out;                          // [N,128]
    float* o_xs = out + (size_t)NH;             // [N,128]
    float* o_u  = out + 2ull * NH;              // [N,64]
    float* o_s  = o_u + (size_t)NN * 64;        // [N,64]

    const int GEMM_GRID  = (NN + 127) / 128;    // 782
    const int WARP_GRID  = NN * 32 / 256;       // 12500
    const int ELT_GRID   = NN * (HH / 4) / 256; // 12500
    const int EDGE_GRID  = EE * 32 / 256;       // 62500

    auto conv = [&](const float* xsrc, const float* xtgt,
                    const float* Ws, const float* Wt, const float* a,
                    const int* si, const int* ti,
                    float* psrc, float* ptgt, float* num, float* den,
                    float* outf, int K) {
        sgemm_kernel<128><<<GEMM_GRID, 256>>>(xsrc, Ws, nullptr, psrc, NN, K);
        sgemm_kernel<128><<<GEMM_GRID, 256>>>(xtgt, Wt, nullptr, ptgt, NN, K);
        score_kernel<<<WARP_GRID, 256>>>(psrc, a, s_src);
        score_kernel<<<WARP_GRID, 256>>>(ptgt, a + HH, s_tgt);
        edge_kernel<<<EDGE_GRID, 256>>>(si, ti, psrc, s_src, s_tgt, num, den);
        combine_kernel<<<ELT_GRID, 256>>>(ptgt, num, den, outf);
    };

    // -------- layer 0 (K = 64) --------
    cudaMemsetAsync(num_s, 0, 2ull * NH * sizeof(float), 0);
    cudaMemsetAsync(den_s, 0, 2ull * NN * sizeof(float), 0);
    conv(x_user, x_spot, Ws_us0, Wt_us0, a_us0, e_us, e_us + EE,
         pu, pts, num_s, den_s, h_s, 64);
    conv(x_spot, x_user, Ws_su0, Wt_su0, a_su0, e_su, e_su + EE,
         ps, ptu, num_u, den_u, h_u, 64);

    // -------- layer 1 (K = 128) --------
    cudaMemsetAsync(num_s, 0, 2ull * NH * sizeof(float), 0);
    cudaMemsetAsync(den_s, 0, 2ull * NN * sizeof(float), 0);
    conv(h_u, h_s, Ws_us1, Wt_us1, a_us1, e_us, e_us + EE,
         pu, pts, num_s, den_s, o_xs, 128);
    conv(h_s, h_u, Ws_su1, Wt_su1, a_su1, e_su, e_su + EE,
         ps, ptu, num_u, den_u, o_xu, 128);

    // -------- final per-type linear (N = 64, with bias) --------
    sgemm_kernel<64><<<GEMM_GRID, 256>>>(o_xu, W_out_user, b_out_user, o_u, NN, 128);
    sgemm_kernel<64><<<GEMM_GRID, 256>>>(o_xs, W_out_spot, b_out_spot, o_s, NN, 128);
}